// round 5
// baseline (speedup 1.0000x reference)
#include <cuda_runtime.h>
#include <cstdint>

#define ZB   16384
#define NIN  127
#define NF   128
#define KOUT 128
#define DTS  2080
#define NNF  (NF * NF)
#define RPAIR 8256
#define RPAD  8320          // 65 * 128
#define NCHUNK 65
#define NHALF  130          // 64-r half chunks

// Scratch (device globals)
__device__ __align__(16) float    g_M[KOUT * NNF];              // 8 MB tf32 W@T
__device__ __align__(16) float    g_B[NHALF * 128 * 64];        // packed sym M, permuted
__device__ __align__(16) uint32_t g_pair[RPAD];                 // i | (j<<16)

__device__ __forceinline__ uint32_t f2tf32(float x) {
    uint32_t r;
    asm("cvt.rna.tf32.f32 %0, %1;" : "=r"(r) : "f"(x));
    return r;
}

__device__ __forceinline__ void mma_tf32(float c[4], const uint32_t a[4], const uint32_t b[2]) {
    asm volatile(
        "mma.sync.aligned.m16n8k8.row.col.f32.tf32.tf32.f32 "
        "{%0,%1,%2,%3}, {%4,%5,%6,%7}, {%8,%9}, {%0,%1,%2,%3};"
        : "+f"(c[0]), "+f"(c[1]), "+f"(c[2]), "+f"(c[3])
        : "r"(a[0]), "r"(a[1]), "r"(a[2]), "r"(a[3]), "r"(b[0]), "r"(b[1]));
}

// ---------------------------------------------------------------------------
// Kernel 1: M = W @ T  (unchanged, known good)
// ---------------------------------------------------------------------------
__global__ void __launch_bounds__(256, 1) stage1_kernel(
        const float* __restrict__ W, const float* __restrict__ T) {
    __shared__ float Wsm[128 * 36];
    __shared__ float Bsm[128 * 36];

    const int tid  = threadIdx.x;
    const int lane = tid & 31;
    const int warp = tid >> 5;
    const int gid  = lane >> 2;
    const int tig  = lane & 3;
    const int wm   = warp >> 1;
    const int wn   = warp & 1;
    const int colbase = blockIdx.x * 128;

    float acc[2][8][4];
#pragma unroll
    for (int mf = 0; mf < 2; mf++)
#pragma unroll
        for (int nf = 0; nf < 8; nf++)
#pragma unroll
            for (int q = 0; q < 4; q++) acc[mf][nf][q] = 0.0f;

    for (int kk = 0; kk < DTS; kk += 32) {
        __syncthreads();
#pragma unroll
        for (int e = tid; e < 128 * 32; e += 256) {
            int m = e >> 5, k = e & 31;
            Wsm[m * 36 + k] = W[m * DTS + kk + k];
        }
#pragma unroll
        for (int e = tid; e < 32 * 128; e += 256) {
            int t = e >> 7, n = e & 127;
            Bsm[n * 36 + t] = T[(kk + t) * NNF + colbase + n];
        }
        __syncthreads();

#pragma unroll
        for (int ks = 0; ks < 4; ks++) {
            uint32_t breg[8][2];
#pragma unroll
            for (int nf = 0; nf < 8; nf++) {
                int n0 = wn * 64 + nf * 8 + gid;
                breg[nf][0] = f2tf32(Bsm[n0 * 36 + ks * 8 + tig]);
                breg[nf][1] = f2tf32(Bsm[n0 * 36 + ks * 8 + tig + 4]);
            }
#pragma unroll
            for (int mf = 0; mf < 2; mf++) {
                int r0 = wm * 32 + mf * 16 + gid;
                uint32_t a[4];
                a[0] = f2tf32(Wsm[r0 * 36 + ks * 8 + tig]);
                a[1] = f2tf32(Wsm[(r0 + 8) * 36 + ks * 8 + tig]);
                a[2] = f2tf32(Wsm[r0 * 36 + ks * 8 + tig + 4]);
                a[3] = f2tf32(Wsm[(r0 + 8) * 36 + ks * 8 + tig + 4]);
#pragma unroll
                for (int nf = 0; nf < 8; nf++)
                    mma_tf32(acc[mf][nf], a, breg[nf]);
            }
        }
    }

#pragma unroll
    for (int mf = 0; mf < 2; mf++) {
        int r0 = wm * 32 + mf * 16 + gid;
#pragma unroll
        for (int nf = 0; nf < 8; nf++) {
            int c0 = colbase + wn * 64 + nf * 8 + 2 * tig;
            g_M[r0 * NNF + c0]           = __uint_as_float(f2tf32(acc[mf][nf][0]));
            g_M[r0 * NNF + c0 + 1]       = __uint_as_float(f2tf32(acc[mf][nf][1]));
            g_M[(r0 + 8) * NNF + c0]     = __uint_as_float(f2tf32(acc[mf][nf][2]));
            g_M[(r0 + 8) * NNF + c0 + 1] = __uint_as_float(f2tf32(acc[mf][nf][3]));
        }
    }
}

// ---------------------------------------------------------------------------
// Pair table: r -> (i, j), i <= j, i-major
// ---------------------------------------------------------------------------
__global__ void build_pairs_kernel() {
    int i = blockIdx.x, j = threadIdx.x;
    if (j >= i) {
        int r = i * NF - (i * (i - 1)) / 2 + (j - i);
        g_pair[r] = (uint32_t)i | ((uint32_t)j << 16);
    }
    if (i == 0 && j < RPAD - RPAIR) g_pair[RPAIR + j] = 0;
}

// ---------------------------------------------------------------------------
// Pack: Bpack[k, r] = M[k,i,j] (+ M[k,j,i] if i<j), tf32, permuted half-chunk
// layout: g_B[h][k][w], w = klp*16 + tig*4 + e encodes
//   r = h*64 + (2*klp + (e>>1))*8 + tig + 4*(e&1)
// ---------------------------------------------------------------------------
__global__ void pack_kernel() {
    int h = blockIdx.x, k = blockIdx.y, w = threadIdx.x;   // w in [0,64)
    int klp = w >> 4, q = (w >> 2) & 3, e = w & 3;
    int r = h * 64 + (2 * klp + (e >> 1)) * 8 + q + 4 * (e & 1);
    float v = 0.0f;
    if (r < RPAIR) {
        uint32_t p = g_pair[r];
        int i = p & 0xFFFF, j = p >> 16;
        v = g_M[k * NNF + i * NF + j];
        if (i != j) v += g_M[k * NNF + j * NF + i];
    }
    g_B[(h * 128 + k) * 64 + w] = __uint_as_float(f2tf32(v));
}

// ---------------------------------------------------------------------------
// Stage 2: 512 threads / 16 warps, warp tile 32z x 32k.
// SMEM: fsm [128][129] | A_sm [16384 words, fragment order] | Bh [2][128][80] | pbuf [2][128]
// ---------------------------------------------------------------------------
#define FSTRF 129
#define BSTR  80
#define FSM_WORDS  (128 * FSTRF)          // 16512
#define A_WORDS    16384
#define BH_WORDS   (128 * BSTR)           // 10240
#define S2_SMEM ((FSM_WORDS + A_WORDS + 2 * BH_WORDS + 256) * 4)  // 214528 B

__global__ void __launch_bounds__(512, 1) stage2_kernel(
        const float* __restrict__ feat, float* __restrict__ out) {
    extern __shared__ float sm[];
    float*    fsm  = sm;
    float*    A_sm = sm + FSM_WORDS;
    float*    bh0  = A_sm + A_WORDS;
    float*    bh1  = bh0 + BH_WORDS;
    uint32_t* pbuf = (uint32_t*)(bh1 + BH_WORDS);   // [2][128]

    const int tid  = threadIdx.x;
    const int lane = tid & 31;
    const int warp = tid >> 5;
    const int gid  = lane >> 2;
    const int tig  = lane & 3;
    const int wm   = warp >> 2;    // 0..3  (z)
    const int wn   = warp & 3;     // 0..3  (k)
    const int zbase = blockIdx.x * 128;

    // Stage f tile (ones column fused)
    for (int e = tid; e < 128 * 128; e += 512) {
        int z = e >> 7, c = e & 127;
        fsm[z * FSTRF + c] =
            (c == 0) ? 1.0f : feat[(size_t)(zbase + z) * NIN + (c - 1)];
    }

    float acc[2][4][4];
#pragma unroll
    for (int mf = 0; mf < 2; mf++)
#pragma unroll
        for (int nf = 0; nf < 4; nf++)
#pragma unroll
            for (int q = 0; q < 4; q++) acc[mf][nf][q] = 0.0f;

    auto prefetch_half = [&](int h, float* buf) {
#pragma unroll
        for (int t = 0; t < 4; t++) {
            int cc = tid + 512 * t;                 // 2048 16B chunks
            int k = cc >> 4, grp = cc & 15;
            uint32_t dst = (uint32_t)__cvta_generic_to_shared(buf + k * BSTR + grp * 4);
            size_t src = (size_t)__cvta_generic_to_global(g_B + (size_t)(h * 128 + k) * 64 + grp * 4);
            asm volatile("cp.async.cg.shared.global [%0], [%1], 16;" :: "r"(dst), "l"(src));
        }
    };
    auto prefetch_pairs = [&](int c, int bi) {
        if (tid < 32) {
            uint32_t dst = (uint32_t)__cvta_generic_to_shared(pbuf + bi * 128 + tid * 4);
            size_t src = (size_t)__cvta_generic_to_global(g_pair + c * 128 + tid * 4);
            asm volatile("cp.async.ca.shared.global [%0], [%1], 16;" :: "r"(dst), "l"(src));
        }
    };

    // Prologue: G0 = {pairs(0), Bh(0)}
    prefetch_pairs(0, 0);
    prefetch_half(0, bh0);
    asm volatile("cp.async.commit_group;" ::: "memory");

    for (int c = 0; c < NCHUNK; ++c) {
        const uint32_t* pcur = pbuf + (c & 1) * 128;

        __syncthreads();                                    // prior MMA done (bh1, A free)
        prefetch_half(2 * c + 1, bh1);
        if (c + 1 < NCHUNK) prefetch_pairs(c + 1, (c + 1) & 1);
        asm volatile("cp.async.commit_group;" ::: "memory");
        asm volatile("cp.async.wait_group 1;" ::: "memory");  // Bh(2c), pairs(c) done
        __syncthreads();                                      // visibility

        // ---- cooperative A build: A[z,r]=tf32(f_i*f_j), fragment order -----
        // group g = wmq*32 + ksq*2 + mfq; thread writes float4 at g*128+lane*4
#pragma unroll
        for (int step = 0; step < 8; step++) {
            int g = step * 16 + warp;
            int mfq = g & 1;
            int ksq = (g >> 1) & 15;
            int wmq = g >> 5;
            uint32_t p0 = pcur[ksq * 8 + tig];
            uint32_t p1 = pcur[ksq * 8 + tig + 4];
            int i0 = p0 & 0xFFFF, j0 = p0 >> 16;
            int i1 = p1 & 0xFFFF, j1 = p1 >> 16;
            const float* fz0 = fsm + (wmq * 32 + mfq * 16 + gid) * FSTRF;
            const float* fz8 = fz0 + 8 * FSTRF;
            float4 v;
            v.x = __uint_as_float(f2tf32(fz0[i0] * fz0[j0]));
            v.y = __uint_as_float(f2tf32(fz8[i0] * fz8[j0]));
            v.z = __uint_as_float(f2tf32(fz0[i1] * fz0[j1]));
            v.w = __uint_as_float(f2tf32(fz8[i1] * fz8[j1]));
            *(float4*)(A_sm + (size_t)(step * 512 + tid) * 4) = v;
        }
        __syncthreads();                                      // A ready

        // ---- MMA half 0 (chunk k-steps 0..7, buffer bh0) ----
#pragma unroll
        for (int klp = 0; klp < 4; klp++) {
            uint32_t bq[4][4];
#pragma unroll
            for (int nf = 0; nf < 4; nf++) {
                int n0 = wn * 32 + nf * 8 + gid;
                float4 v = *(const float4*)(bh0 + n0 * BSTR + klp * 16 + tig * 4);
                bq[nf][0] = __float_as_uint(v.x);
                bq[nf][1] = __float_as_uint(v.y);
                bq[nf][2] = __float_as_uint(v.z);
                bq[nf][3] = __float_as_uint(v.w);
            }
#pragma unroll
            for (int s = 0; s < 2; s++) {
                int ks = klp * 2 + s;
#pragma unroll
                for (int mf = 0; mf < 2; mf++) {
                    int g = wm * 32 + ks * 2 + mf;
                    const float4 av = *(const float4*)(A_sm + (size_t)g * 128 + lane * 4);
                    uint32_t a[4] = { __float_as_uint(av.x), __float_as_uint(av.y),
                                      __float_as_uint(av.z), __float_as_uint(av.w) };
#pragma unroll
                    for (int nf = 0; nf < 4; nf++) {
                        uint32_t bb[2] = { bq[nf][2 * s], bq[nf][2 * s + 1] };
                        mma_tf32(acc[mf][nf], a, bb);
                    }
                }
            }
        }
        __syncthreads();                                      // bh0 free

        if (2 * c + 2 < NHALF) {
            prefetch_half(2 * c + 2, bh0);
            asm volatile("cp.async.commit_group;" ::: "memory");
            asm volatile("cp.async.wait_group 1;" ::: "memory");  // Bh(2c+1) done
        } else {
            asm volatile("cp.async.wait_group 0;" ::: "memory");
        }
        __syncthreads();                                      // visibility

        // ---- MMA half 1 (chunk k-steps 8..15, buffer bh1) ----
#pragma unroll
        for (int klp = 0; klp < 4; klp++) {
            uint32_t bq[4][4];
#pragma unroll
            for (int nf = 0; nf < 4; nf++) {
                int n0 = wn * 32 + nf * 8 + gid;
                float4 v = *(const float4*)(bh1 + n0 * BSTR + klp * 16 + tig * 4);
                bq[nf][0] = __float_as_uint(v.x);
                bq[nf][1] = __float_as_uint(v.y);
                bq[nf][2] = __float_as_uint(v.z);
                bq[nf][3] = __float_as_uint(v.w);
            }
#pragma unroll
            for (int s = 0; s < 2; s++) {
                int ks = 8 + klp * 2 + s;
#pragma unroll
                for (int mf = 0; mf < 2; mf++) {
                    int g = wm * 32 + ks * 2 + mf;
                    const float4 av = *(const float4*)(A_sm + (size_t)g * 128 + lane * 4);
                    uint32_t a[4] = { __float_as_uint(av.x), __float_as_uint(av.y),
                                      __float_as_uint(av.z), __float_as_uint(av.w) };
#pragma unroll
                    for (int nf = 0; nf < 4; nf++) {
                        uint32_t bb[2] = { bq[nf][2 * s], bq[nf][2 * s + 1] };
                        mma_tf32(acc[mf][nf], a, bb);
                    }
                }
            }
        }
    }

    // Epilogue
#pragma unroll
    for (int mf = 0; mf < 2; mf++) {
        int r0 = wm * 32 + mf * 16 + gid;
#pragma unroll
        for (int nf = 0; nf < 4; nf++) {
            int c0 = wn * 32 + nf * 8 + 2 * tig;
            out[(zbase + r0) * KOUT + c0]         = acc[mf][nf][0];
            out[(zbase + r0) * KOUT + c0 + 1]     = acc[mf][nf][1];
            out[(zbase + r0 + 8) * KOUT + c0]     = acc[mf][nf][2];
            out[(zbase + r0 + 8) * KOUT + c0 + 1] = acc[mf][nf][3];
        }
    }
}

// ---------------------------------------------------------------------------
extern "C" void kernel_launch(void* const* d_in, const int* in_sizes, int n_in,
                              void* d_out, int out_size) {
    const float* feat = nullptr;
    const float* W    = nullptr;
    const float* T    = nullptr;
    for (int i = 0; i < n_in; i++) {
        if      (in_sizes[i] == ZB * NIN)   feat = (const float*)d_in[i];
        else if (in_sizes[i] == KOUT * DTS) W    = (const float*)d_in[i];
        else if (in_sizes[i] == DTS * NNF)  T    = (const float*)d_in[i];
    }
    float* out = (float*)d_out;

    cudaFuncSetAttribute(stage2_kernel,
                         cudaFuncAttributeMaxDynamicSharedMemorySize, S2_SMEM);

    build_pairs_kernel<<<128, 128>>>();
    stage1_kernel<<<128, 256>>>(W, T);
    pack_kernel<<<dim3(NHALF, KOUT), 64>>>();
    stage2_kernel<<<128, 512, S2_SMEM>>>(feat, out);
}

// round 6
// speedup vs baseline: 1.1891x; 1.1891x over previous
#include <cuda_runtime.h>
#include <cstdint>

#define ZB   16384
#define NIN  127
#define NF   128
#define KOUT 128
#define DTS  2080
#define NNF  (NF * NF)
#define RPAIR 8256
#define RPAD  8320          // 65 * 128
#define NCHUNK 65
#define NHALF  130          // 64-r half chunks

// Scratch (device globals)
__device__ __align__(16) float    g_M[KOUT * NNF];              // 8 MB tf32 W@T
__device__ __align__(16) float    g_B[NHALF * 128 * 64];        // packed sym M, permuted
__device__ __align__(16) uint32_t g_pair[RPAD];                 // i | (j<<16)

__device__ __forceinline__ uint32_t f2tf32(float x) {
    uint32_t r;
    asm("cvt.rna.tf32.f32 %0, %1;" : "=r"(r) : "f"(x));
    return r;
}

__device__ __forceinline__ void mma_tf32(float c[4], const uint32_t a[4], const uint32_t b[2]) {
    asm volatile(
        "mma.sync.aligned.m16n8k8.row.col.f32.tf32.tf32.f32 "
        "{%0,%1,%2,%3}, {%4,%5,%6,%7}, {%8,%9}, {%0,%1,%2,%3};"
        : "+f"(c[0]), "+f"(c[1]), "+f"(c[2]), "+f"(c[3])
        : "r"(a[0]), "r"(a[1]), "r"(a[2]), "r"(a[3]), "r"(b[0]), "r"(b[1]));
}

#define NB_SYNC(id)   asm volatile("bar.sync %0, 512;"   :: "r"(id) : "memory")
#define NB_ARRIVE(id) asm volatile("bar.arrive %0, 512;" :: "r"(id) : "memory")

// ---------------------------------------------------------------------------
// Kernel 1: M = W @ T  (unchanged, known good)
// ---------------------------------------------------------------------------
__global__ void __launch_bounds__(256, 1) stage1_kernel(
        const float* __restrict__ W, const float* __restrict__ T) {
    __shared__ float Wsm[128 * 36];
    __shared__ float Bsm[128 * 36];

    const int tid  = threadIdx.x;
    const int lane = tid & 31;
    const int warp = tid >> 5;
    const int gid  = lane >> 2;
    const int tig  = lane & 3;
    const int wm   = warp >> 1;
    const int wn   = warp & 1;
    const int colbase = blockIdx.x * 128;

    float acc[2][8][4];
#pragma unroll
    for (int mf = 0; mf < 2; mf++)
#pragma unroll
        for (int nf = 0; nf < 8; nf++)
#pragma unroll
            for (int q = 0; q < 4; q++) acc[mf][nf][q] = 0.0f;

    for (int kk = 0; kk < DTS; kk += 32) {
        __syncthreads();
#pragma unroll
        for (int e = tid; e < 128 * 32; e += 256) {
            int m = e >> 5, k = e & 31;
            Wsm[m * 36 + k] = W[m * DTS + kk + k];
        }
#pragma unroll
        for (int e = tid; e < 32 * 128; e += 256) {
            int t = e >> 7, n = e & 127;
            Bsm[n * 36 + t] = T[(kk + t) * NNF + colbase + n];
        }
        __syncthreads();

#pragma unroll
        for (int ks = 0; ks < 4; ks++) {
            uint32_t breg[8][2];
#pragma unroll
            for (int nf = 0; nf < 8; nf++) {
                int n0 = wn * 64 + nf * 8 + gid;
                breg[nf][0] = f2tf32(Bsm[n0 * 36 + ks * 8 + tig]);
                breg[nf][1] = f2tf32(Bsm[n0 * 36 + ks * 8 + tig + 4]);
            }
#pragma unroll
            for (int mf = 0; mf < 2; mf++) {
                int r0 = wm * 32 + mf * 16 + gid;
                uint32_t a[4];
                a[0] = f2tf32(Wsm[r0 * 36 + ks * 8 + tig]);
                a[1] = f2tf32(Wsm[(r0 + 8) * 36 + ks * 8 + tig]);
                a[2] = f2tf32(Wsm[r0 * 36 + ks * 8 + tig + 4]);
                a[3] = f2tf32(Wsm[(r0 + 8) * 36 + ks * 8 + tig + 4]);
#pragma unroll
                for (int nf = 0; nf < 8; nf++)
                    mma_tf32(acc[mf][nf], a, breg[nf]);
            }
        }
    }

#pragma unroll
    for (int mf = 0; mf < 2; mf++) {
        int r0 = wm * 32 + mf * 16 + gid;
#pragma unroll
        for (int nf = 0; nf < 8; nf++) {
            int c0 = colbase + wn * 64 + nf * 8 + 2 * tig;
            g_M[r0 * NNF + c0]           = __uint_as_float(f2tf32(acc[mf][nf][0]));
            g_M[r0 * NNF + c0 + 1]       = __uint_as_float(f2tf32(acc[mf][nf][1]));
            g_M[(r0 + 8) * NNF + c0]     = __uint_as_float(f2tf32(acc[mf][nf][2]));
            g_M[(r0 + 8) * NNF + c0 + 1] = __uint_as_float(f2tf32(acc[mf][nf][3]));
        }
    }
}

// ---------------------------------------------------------------------------
// Pair table: r -> (i, j), i <= j, i-major
// ---------------------------------------------------------------------------
__global__ void build_pairs_kernel() {
    int i = blockIdx.x, j = threadIdx.x;
    if (j >= i) {
        int r = i * NF - (i * (i - 1)) / 2 + (j - i);
        g_pair[r] = (uint32_t)i | ((uint32_t)j << 16);
    }
    if (i == 0 && j < RPAD - RPAIR) g_pair[RPAIR + j] = 0;
}

// ---------------------------------------------------------------------------
// Pack: Bpack[k, r] = M[k,i,j] (+ M[k,j,i] if i<j), tf32, permuted half-chunk
// layout: g_B[h][k][w], w = klp*16 + tig*4 + e encodes
//   r = h*64 + (2*klp + (e>>1))*8 + tig + 4*(e&1)
// ---------------------------------------------------------------------------
__global__ void pack_kernel() {
    int h = blockIdx.x, k = blockIdx.y, w = threadIdx.x;   // w in [0,64)
    int klp = w >> 4, q = (w >> 2) & 3, e = w & 3;
    int r = h * 64 + (2 * klp + (e >> 1)) * 8 + q + 4 * (e & 1);
    float v = 0.0f;
    if (r < RPAIR) {
        uint32_t p = g_pair[r];
        int i = p & 0xFFFF, j = p >> 16;
        v = g_M[k * NNF + i * NF + j];
        if (i != j) v += g_M[k * NNF + j * NF + i];
    }
    g_B[(h * 128 + k) * 64 + w] = __uint_as_float(f2tf32(v));
}

// ---------------------------------------------------------------------------
// Stage 2: warp-specialized. 512 threads: warps 0-7 consumers (32z x 64k warp
// tiles over 128z x 128k), warps 8-15 producers (A build + B cp.async, per
// 64-r half, double buffered). Named barriers: RDY = 1+p, FRE = 3+p.
// SMEM (words): fsm[16512] | A[2][8192] frag-order | Bh[2][128*80] | total 53376
// ---------------------------------------------------------------------------
#define FSTRF 129
#define BSTR  80
#define FSM_WORDS  (128 * FSTRF)          // 16512
#define AH_WORDS   8192                   // 64 groups * 128 words
#define BH_WORDS   (128 * BSTR)           // 10240
#define S2_SMEM ((FSM_WORDS + 2 * AH_WORDS + 2 * BH_WORDS) * 4)  // 213504 B

__global__ void __launch_bounds__(512, 1) stage2_kernel(
        const float* __restrict__ feat, float* __restrict__ out) {
    extern __shared__ float sm[];
    float* fsm = sm;
    float* Abuf[2] = { sm + FSM_WORDS, sm + FSM_WORDS + AH_WORDS };
    float* Bbuf[2] = { sm + FSM_WORDS + 2 * AH_WORDS,
                       sm + FSM_WORDS + 2 * AH_WORDS + BH_WORDS };

    const int tid  = threadIdx.x;
    const int lane = tid & 31;
    const int warp = tid >> 5;
    const int gid  = lane >> 2;
    const int tig  = lane & 3;
    const int zbase = blockIdx.x * 128;

    // Stage f tile (ones column fused) — all 512 threads
    for (int e = tid; e < 128 * 128; e += 512) {
        int z = e >> 7, c = e & 127;
        fsm[z * FSTRF + c] =
            (c == 0) ? 1.0f : feat[(size_t)(zbase + z) * NIN + (c - 1)];
    }
    __syncthreads();

    if (warp >= 8) {
        // ===================== PRODUCER =====================
        const int ptid = tid - 256;           // 0..255
        const int pw   = warp - 8;            // 0..7

        for (int h = 0; h < NHALF; ++h) {
            const int p = h & 1;
            if (h >= 2) NB_SYNC(3 + p);       // wait consumer freed buffer p

            // B(h) -> Bbuf[p] via cp.async (2048 x 16B)
            {
                float* buf = Bbuf[p];
                const float* src = g_B + (size_t)h * 8192;
#pragma unroll
                for (int t = 0; t < 8; t++) {
                    int cc = ptid + 256 * t;
                    int k = cc >> 4, grp = cc & 15;
                    uint32_t dst = (uint32_t)__cvta_generic_to_shared(buf + k * BSTR + grp * 4);
                    asm volatile("cp.async.cg.shared.global [%0], [%1], 16;"
                                 :: "r"(dst), "l"(src + k * 64 + grp * 4));
                }
                asm volatile("cp.async.commit_group;" ::: "memory");
            }

            // A(h) build into Abuf[p], fragment order: g = wm*16 + ks*2 + mf
            {
                float* abuf = Abuf[p];
                const uint32_t* pb = g_pair + h * 64;
#pragma unroll
                for (int step = 0; step < 8; step++) {
                    int g = step * 8 + pw;
                    int mfq = g & 1;
                    int ksq = (g >> 1) & 7;
                    int wmq = g >> 4;
                    uint32_t p0 = __ldg(pb + ksq * 8 + tig);
                    uint32_t p1 = __ldg(pb + ksq * 8 + tig + 4);
                    int i0 = p0 & 0xFFFF, j0 = p0 >> 16;
                    int i1 = p1 & 0xFFFF, j1 = p1 >> 16;
                    const float* fz0 = fsm + (wmq * 32 + mfq * 16 + gid) * FSTRF;
                    const float* fz8 = fz0 + 8 * FSTRF;
                    uint32_t v0 = f2tf32(fz0[i0] * fz0[j0]);
                    uint32_t v1 = f2tf32(fz8[i0] * fz8[j0]);
                    uint32_t v2 = f2tf32(fz0[i1] * fz0[j1]);
                    uint32_t v3 = f2tf32(fz8[i1] * fz8[j1]);
                    uint32_t dst = (uint32_t)__cvta_generic_to_shared(
                        abuf + (size_t)g * 128 + lane * 4);
                    asm volatile("st.shared.v4.b32 [%0], {%1, %2, %3, %4};"
                                 :: "r"(dst), "r"(v0), "r"(v1), "r"(v2), "r"(v3));
                }
            }

            asm volatile("cp.async.wait_group 0;" ::: "memory");
            NB_ARRIVE(1 + p);                 // buffer p ready
        }
    } else {
        // ===================== CONSUMER =====================
        const int wm = warp >> 1;             // 0..3 (z)
        const int wn = warp & 1;              // 0..1 (k)

        float acc[2][8][4];
#pragma unroll
        for (int mf = 0; mf < 2; mf++)
#pragma unroll
            for (int nf = 0; nf < 8; nf++)
#pragma unroll
                for (int q = 0; q < 4; q++) acc[mf][nf][q] = 0.0f;

        for (int h = 0; h < NHALF; ++h) {
            const int p = h & 1;
            NB_SYNC(1 + p);                   // buffer p ready
            const float* abuf = Abuf[p];
            const float* bbuf = Bbuf[p];

#pragma unroll
            for (int klp = 0; klp < 4; klp++) {
                // A frags for ks = 2klp, 2klp+1; mf = 0,1  -> a4[s*2+mf]
                uint32_t a4[4][4];
#pragma unroll
                for (int s = 0; s < 2; s++)
#pragma unroll
                    for (int mf = 0; mf < 2; mf++) {
                        int g = wm * 16 + (2 * klp + s) * 2 + mf;
                        float4 v = *(const float4*)(abuf + (size_t)g * 128 + lane * 4);
                        a4[s * 2 + mf][0] = __float_as_uint(v.x);
                        a4[s * 2 + mf][1] = __float_as_uint(v.y);
                        a4[s * 2 + mf][2] = __float_as_uint(v.z);
                        a4[s * 2 + mf][3] = __float_as_uint(v.w);
                    }
#pragma unroll
                for (int nf = 0; nf < 8; nf++) {
                    int n0 = wn * 64 + nf * 8 + gid;
                    float4 v = *(const float4*)(bbuf + n0 * BSTR + klp * 16 + tig * 4);
                    uint32_t b0[2] = { __float_as_uint(v.x), __float_as_uint(v.y) };
                    uint32_t b1[2] = { __float_as_uint(v.z), __float_as_uint(v.w) };
#pragma unroll
                    for (int mf = 0; mf < 2; mf++) {
                        mma_tf32(acc[mf][nf], a4[0 * 2 + mf], b0);
                        mma_tf32(acc[mf][nf], a4[1 * 2 + mf], b1);
                    }
                }
            }
            NB_ARRIVE(3 + p);                 // buffer p free
        }

        // Epilogue
#pragma unroll
        for (int mf = 0; mf < 2; mf++) {
            int r0 = wm * 32 + mf * 16 + gid;
#pragma unroll
            for (int nf = 0; nf < 8; nf++) {
                int c0 = wn * 64 + nf * 8 + 2 * tig;
                out[(zbase + r0) * KOUT + c0]         = acc[mf][nf][0];
                out[(zbase + r0) * KOUT + c0 + 1]     = acc[mf][nf][1];
                out[(zbase + r0 + 8) * KOUT + c0]     = acc[mf][nf][2];
                out[(zbase + r0 + 8) * KOUT + c0 + 1] = acc[mf][nf][3];
            }
        }
    }
}

// ---------------------------------------------------------------------------
extern "C" void kernel_launch(void* const* d_in, const int* in_sizes, int n_in,
                              void* d_out, int out_size) {
    const float* feat = nullptr;
    const float* W    = nullptr;
    const float* T    = nullptr;
    for (int i = 0; i < n_in; i++) {
        if      (in_sizes[i] == ZB * NIN)   feat = (const float*)d_in[i];
        else if (in_sizes[i] == KOUT * DTS) W    = (const float*)d_in[i];
        else if (in_sizes[i] == DTS * NNF)  T    = (const float*)d_in[i];
    }
    float* out = (float*)d_out;

    cudaFuncSetAttribute(stage2_kernel,
                         cudaFuncAttributeMaxDynamicSharedMemorySize, S2_SMEM);

    build_pairs_kernel<<<128, 128>>>();
    stage1_kernel<<<128, 256>>>(W, T);
    pack_kernel<<<dim3(NHALF, KOUT), 64>>>();
    stage2_kernel<<<128, 512, S2_SMEM>>>(feat, out);
}